// round 7
// baseline (speedup 1.0000x reference)
#include <cuda_runtime.h>

// RoIBridge: masked positional-embedding gather, round 6.
// Thread handles TWO rows (r, r+ROWS/2), lane d4 = tid&15 covering one float4
// column across all 4 coords of both rows.
//  - all long-latency loads (2x obj, 2x frac4) issued unconditionally and
//    independently up front: MLP=4 DRAM-class loads, no obj->frac serial chain
//  - 8 independent L1-resident table gathers (table = 57.6 KB, L1-resident)
//  - 8 streaming stores (__stcs), each STG.128 fully coalesced
// 128 B of output per thread per dependent chain.

static constexpr int IMAGE_SIZE = 224;
static constexpr int ROWS = 2048 * 128;     // 262144
static constexpr int HALF = ROWS / 2;

__device__ __forceinline__ int clamp_idx(float f) {
    float x = fminf(fmaxf(f * (float)IMAGE_SIZE, 0.0f), (float)IMAGE_SIZE);
    return (int)x;   // trunc toward zero == astype(int32) for x >= 0
}

__global__ void __launch_bounds__(256, 8)
roibridge_kernel(const float4* __restrict__ frac4,   // [ROWS]
                 const int*    __restrict__ obj,     // [ROWS]
                 const float4* __restrict__ table4,  // [225 * 16]
                 float4*       __restrict__ out)     // [ROWS * 64]
{
    int tid = blockIdx.x * blockDim.x + threadIdx.x;   // 0 .. HALF*16-1
    int g   = tid >> 4;          // row group
    int d4  = tid & 15;          // float4 lane within coord embedding
    int r0  = g;
    int r1  = g + HALF;

    // ---- batch all long-latency loads, fully independent (MLP=4) ----
    int    o0 = __ldg(obj + r0);
    int    o1 = __ldg(obj + r1);
    float4 f0 = __ldg(frac4 + r0);
    float4 f1 = __ldg(frac4 + r1);

    const float4 z = make_float4(0.f, 0.f, 0.f, 0.f);
    float4 a0 = z, a1 = z, a2 = z, a3 = z;
    float4 b0 = z, b1 = z, b2 = z, b3 = z;

    if (o0 == 1) {
        a0 = __ldg(table4 + clamp_idx(f0.x) * 16 + d4);
        a1 = __ldg(table4 + clamp_idx(f0.y) * 16 + d4);
        a2 = __ldg(table4 + clamp_idx(f0.z) * 16 + d4);
        a3 = __ldg(table4 + clamp_idx(f0.w) * 16 + d4);
    }
    if (o1 == 1) {
        b0 = __ldg(table4 + clamp_idx(f1.x) * 16 + d4);
        b1 = __ldg(table4 + clamp_idx(f1.y) * 16 + d4);
        b2 = __ldg(table4 + clamp_idx(f1.z) * 16 + d4);
        b3 = __ldg(table4 + clamp_idx(f1.w) * 16 + d4);
    }

    float4* p0 = out + r0 * 64 + d4;
    __stcs(p0 +  0, a0);
    __stcs(p0 + 16, a1);
    __stcs(p0 + 32, a2);
    __stcs(p0 + 48, a3);

    float4* p1 = out + r1 * 64 + d4;
    __stcs(p1 +  0, b0);
    __stcs(p1 + 16, b1);
    __stcs(p1 + 32, b2);
    __stcs(p1 + 48, b3);
}

extern "C" void kernel_launch(void* const* d_in, const int* in_sizes, int n_in,
                              void* d_out, int out_size)
{
    const float4* frac4 = (const float4*)d_in[0];   // [2048,128,4] f32
    const int*    obj   = (const int*)d_in[1];      // [2048,128] i32
    const float4* table = (const float4*)d_in[2];   // [225,64] f32
    float4* out = (float4*)d_out;

    const int total = HALF * 16;                    // 2,097,152 threads
    const int threads = 256;
    const int blocks = total / threads;             // 8,192

    roibridge_kernel<<<blocks, threads>>>(frac4, obj, table, out);
}

// round 8
// speedup vs baseline: 1.2712x; 1.2712x over previous
#include <cuda_runtime.h>

// RoIBridge round 8: smem-staged table + persistent grid.
// R5/R6 showed L1TEX (80%+) is the ceiling: it carries BOTH the 268MB of
// table gathers and the 268MB store stream. Staging the 57.6KB table in
// shared memory moves gathers onto the smem crossbar, leaving L1TEX for
// stores only.
//  - 456 blocks (152 SMs x 3, smem-limited), grid-stride over (row, d4)
//  - per item: obj + frac4 global loads (independent), 4 conflict-free
//    LDS.128 gathers, 4 coalesced __stcs stores (single write stream/warp)

static constexpr int IMAGE_SIZE = 224;
static constexpr int ROWS = 2048 * 128;       // 262144
static constexpr int TABLE_F4 = 225 * 16;     // 3600 float4 = 57600 B
static constexpr int WORK = ROWS * 16;        // 4,194,304 items

__device__ __forceinline__ int clamp_idx(float f) {
    float x = fminf(fmaxf(f * (float)IMAGE_SIZE, 0.0f), (float)IMAGE_SIZE);
    return (int)x;   // trunc toward zero == astype(int32), x >= 0
}

extern __shared__ float4 s_tab[];             // [225*16]

__global__ void __launch_bounds__(256)
roibridge_kernel(const float4* __restrict__ frac4,   // [ROWS]
                 const int*    __restrict__ obj,     // [ROWS]
                 const float4* __restrict__ table4,  // [225*16]
                 float4*       __restrict__ out)     // [ROWS*64]
{
    // ---- stage table into shared memory (one-time per block) ----
    for (int i = threadIdx.x; i < TABLE_F4; i += blockDim.x)
        s_tab[i] = table4[i];
    __syncthreads();

    const int stride = gridDim.x * blockDim.x;
    const float4 z = make_float4(0.f, 0.f, 0.f, 0.f);

    #pragma unroll 2
    for (int tid = blockIdx.x * blockDim.x + threadIdx.x; tid < WORK; tid += stride) {
        int row = tid >> 4;
        int d4  = tid & 15;

        int    o = __ldg(obj + row);
        float4 f = __ldg(frac4 + row);

        float4 v0 = z, v1 = z, v2 = z, v3 = z;
        if (o == 1) {
            v0 = s_tab[clamp_idx(f.x) * 16 + d4];
            v1 = s_tab[clamp_idx(f.y) * 16 + d4];
            v2 = s_tab[clamp_idx(f.z) * 16 + d4];
            v3 = s_tab[clamp_idx(f.w) * 16 + d4];
        }

        float4* p = out + row * 64 + d4;
        __stcs(p +  0, v0);
        __stcs(p + 16, v1);
        __stcs(p + 32, v2);
        __stcs(p + 48, v3);
    }
}

extern "C" void kernel_launch(void* const* d_in, const int* in_sizes, int n_in,
                              void* d_out, int out_size)
{
    const float4* frac4 = (const float4*)d_in[0];   // [2048,128,4] f32
    const int*    obj   = (const int*)d_in[1];      // [2048,128] i32
    const float4* table = (const float4*)d_in[2];   // [225,64] f32
    float4* out = (float4*)d_out;

    const int smem_bytes = TABLE_F4 * sizeof(float4);   // 57600
    cudaFuncSetAttribute(roibridge_kernel,
                         cudaFuncAttributeMaxDynamicSharedMemorySize, smem_bytes);

    const int threads = 256;
    const int blocks = 152 * 3;   // GB300: 152 SMs, 3 blocks/SM (smem-limited)

    roibridge_kernel<<<blocks, threads, smem_bytes>>>(frac4, obj, table, out);
}

// round 9
// speedup vs baseline: 1.3011x; 1.0235x over previous
#include <cuda_runtime.h>

// RoIBridge round 9: smem table + 512-thread blocks (occ 36->75%) +
// 2-ADJACENT-row batching with front-batched independent LDGs.
//  - 456 persistent blocks (152 SMs x 3, smem-limited at 57.6KB)
//  - thread item = (pair p, lane d4): rows 2p and 2p+1
//  - 4 independent global loads up front (2x obj, 2x frac4), MLP=4
//  - 8 conflict-free LDS.128 gathers from the staged table
//  - 8 __stcs stores; warp covers one contiguous 4KB output span

static constexpr int IMAGE_SIZE = 224;
static constexpr int ROWS = 2048 * 128;       // 262144
static constexpr int TABLE_F4 = 225 * 16;     // 3600 float4 = 57600 B
static constexpr int PAIRS = ROWS / 2;        // 131072
static constexpr int WORK = PAIRS * 16;       // 2,097,152 items

__device__ __forceinline__ int clamp_idx(float f) {
    float x = fminf(fmaxf(f * (float)IMAGE_SIZE, 0.0f), (float)IMAGE_SIZE);
    return (int)x;   // trunc toward zero == astype(int32), x >= 0
}

extern __shared__ float4 s_tab[];             // [225*16]

__global__ void __launch_bounds__(512)
roibridge_kernel(const float4* __restrict__ frac4,   // [ROWS]
                 const int*    __restrict__ obj,     // [ROWS]
                 const float4* __restrict__ table4,  // [225*16]
                 float4*       __restrict__ out)     // [ROWS*64]
{
    // ---- stage table into shared memory (one-time per block) ----
    for (int i = threadIdx.x; i < TABLE_F4; i += blockDim.x)
        s_tab[i] = table4[i];
    __syncthreads();

    const int stride = gridDim.x * blockDim.x;
    const float4 z = make_float4(0.f, 0.f, 0.f, 0.f);

    for (int tid = blockIdx.x * blockDim.x + threadIdx.x; tid < WORK; tid += stride) {
        int p   = tid >> 4;          // row pair
        int d4  = tid & 15;          // float4 lane
        int r0  = p * 2;
        int r1  = r0 + 1;

        // front-batched, fully independent long-latency loads (MLP=4)
        int    o0 = __ldg(obj + r0);
        int    o1 = __ldg(obj + r1);
        float4 f0 = __ldg(frac4 + r0);
        float4 f1 = __ldg(frac4 + r1);

        float4 a0 = z, a1 = z, a2 = z, a3 = z;
        float4 b0 = z, b1 = z, b2 = z, b3 = z;

        if (o0 == 1) {
            a0 = s_tab[clamp_idx(f0.x) * 16 + d4];
            a1 = s_tab[clamp_idx(f0.y) * 16 + d4];
            a2 = s_tab[clamp_idx(f0.z) * 16 + d4];
            a3 = s_tab[clamp_idx(f0.w) * 16 + d4];
        }
        if (o1 == 1) {
            b0 = s_tab[clamp_idx(f1.x) * 16 + d4];
            b1 = s_tab[clamp_idx(f1.y) * 16 + d4];
            b2 = s_tab[clamp_idx(f1.z) * 16 + d4];
            b3 = s_tab[clamp_idx(f1.w) * 16 + d4];
        }

        float4* q0 = out + r0 * 64 + d4;
        __stcs(q0 +  0, a0);
        __stcs(q0 + 16, a1);
        __stcs(q0 + 32, a2);
        __stcs(q0 + 48, a3);

        float4* q1 = out + r1 * 64 + d4;
        __stcs(q1 +  0, b0);
        __stcs(q1 + 16, b1);
        __stcs(q1 + 32, b2);
        __stcs(q1 + 48, b3);
    }
}

extern "C" void kernel_launch(void* const* d_in, const int* in_sizes, int n_in,
                              void* d_out, int out_size)
{
    const float4* frac4 = (const float4*)d_in[0];   // [2048,128,4] f32
    const int*    obj   = (const int*)d_in[1];      // [2048,128] i32
    const float4* table = (const float4*)d_in[2];   // [225,64] f32
    float4* out = (float4*)d_out;

    const int smem_bytes = TABLE_F4 * sizeof(float4);   // 57600
    cudaFuncSetAttribute(roibridge_kernel,
                         cudaFuncAttributeMaxDynamicSharedMemorySize, smem_bytes);

    const int threads = 512;
    const int blocks = 152 * 3;   // 152 SMs, 3 blocks/SM (smem-limited)

    roibridge_kernel<<<blocks, threads, smem_bytes>>>(frac4, obj, table, out);
}

// round 10
// speedup vs baseline: 1.3161x; 1.0116x over previous
#include <cuda_runtime.h>

// RoIBridge round 10: fix the occupancy miss from R9.
// R9 intended 3x512 threads/SM but regs=43 allowed only 2 blocks/SM (occ 41%).
//  - __launch_bounds__(512, 3) caps regs at 40 so 3 blocks fit (48 warps/SM)
//  - row r0 fully processed (LDS gathers + stores) before r1's gathers:
//    halves live float4 accumulators (8 -> 4) to meet the register budget
//  - long-latency loads (2x obj, 2x frac4) remain front-batched, MLP=4
//  - smem-staged table (57.6 KB), conflict-free LDS.128, coalesced __stcs

static constexpr int IMAGE_SIZE = 224;
static constexpr int ROWS = 2048 * 128;       // 262144
static constexpr int TABLE_F4 = 225 * 16;     // 3600 float4 = 57600 B
static constexpr int PAIRS = ROWS / 2;        // 131072
static constexpr int WORK = PAIRS * 16;       // 2,097,152 items

__device__ __forceinline__ int clamp_idx(float f) {
    float x = fminf(fmaxf(f * (float)IMAGE_SIZE, 0.0f), (float)IMAGE_SIZE);
    return (int)x;   // trunc toward zero == astype(int32), x >= 0
}

extern __shared__ float4 s_tab[];             // [225*16]

__global__ void __launch_bounds__(512, 3)
roibridge_kernel(const float4* __restrict__ frac4,   // [ROWS]
                 const int*    __restrict__ obj,     // [ROWS]
                 const float4* __restrict__ table4,  // [225*16]
                 float4*       __restrict__ out)     // [ROWS*64]
{
    // ---- stage table into shared memory (one-time per block) ----
    for (int i = threadIdx.x; i < TABLE_F4; i += blockDim.x)
        s_tab[i] = table4[i];
    __syncthreads();

    const int stride = gridDim.x * blockDim.x;
    const float4 z = make_float4(0.f, 0.f, 0.f, 0.f);

    for (int tid = blockIdx.x * blockDim.x + threadIdx.x; tid < WORK; tid += stride) {
        int p   = tid >> 4;          // row pair
        int d4  = tid & 15;          // float4 lane
        int r0  = p * 2;
        int r1  = r0 + 1;

        // front-batched, fully independent long-latency loads (MLP=4)
        int    o0 = __ldg(obj + r0);
        int    o1 = __ldg(obj + r1);
        float4 f0 = __ldg(frac4 + r0);
        float4 f1 = __ldg(frac4 + r1);

        // ---- row r0: gather + store (only 4 accumulators live) ----
        {
            float4 a0 = z, a1 = z, a2 = z, a3 = z;
            if (o0 == 1) {
                a0 = s_tab[clamp_idx(f0.x) * 16 + d4];
                a1 = s_tab[clamp_idx(f0.y) * 16 + d4];
                a2 = s_tab[clamp_idx(f0.z) * 16 + d4];
                a3 = s_tab[clamp_idx(f0.w) * 16 + d4];
            }
            float4* q = out + r0 * 64 + d4;
            __stcs(q +  0, a0);
            __stcs(q + 16, a1);
            __stcs(q + 32, a2);
            __stcs(q + 48, a3);
        }

        // ---- row r1 ----
        {
            float4 b0 = z, b1 = z, b2 = z, b3 = z;
            if (o1 == 1) {
                b0 = s_tab[clamp_idx(f1.x) * 16 + d4];
                b1 = s_tab[clamp_idx(f1.y) * 16 + d4];
                b2 = s_tab[clamp_idx(f1.z) * 16 + d4];
                b3 = s_tab[clamp_idx(f1.w) * 16 + d4];
            }
            float4* q = out + r1 * 64 + d4;
            __stcs(q +  0, b0);
            __stcs(q + 16, b1);
            __stcs(q + 32, b2);
            __stcs(q + 48, b3);
        }
    }
}

extern "C" void kernel_launch(void* const* d_in, const int* in_sizes, int n_in,
                              void* d_out, int out_size)
{
    const float4* frac4 = (const float4*)d_in[0];   // [2048,128,4] f32
    const int*    obj   = (const int*)d_in[1];      // [2048,128] i32
    const float4* table = (const float4*)d_in[2];   // [225,64] f32
    float4* out = (float4*)d_out;

    const int smem_bytes = TABLE_F4 * sizeof(float4);   // 57600
    cudaFuncSetAttribute(roibridge_kernel,
                         cudaFuncAttributeMaxDynamicSharedMemorySize, smem_bytes);

    const int threads = 512;
    const int blocks = 152 * 3;   // 152 SMs, 3 blocks/SM (smem- and reg-fit)

    roibridge_kernel<<<blocks, threads, smem_bytes>>>(frac4, obj, table, out);
}